// round 8
// baseline (speedup 1.0000x reference)
#include <cuda_runtime.h>
#include <stdint.h>

// weights[T=8] f32; bond_src/dst/type [B=1024,E=512] i32 (+1 node offset);
// out [B,256,256] f32 (256 MiB) -> HBM-write-bound.
// Fused single-pass (R4/R7 structure): per-batch smem hash dedup (reference
// last-write-wins order), bitmap + rank/popcount + compact values, then ONE
// streaming pass writing every line exactly once.
// R8 delta: 256-bit streaming stores (st.global.cs.v8.f32, sm_100+), 32B per
// thread-iteration -> 16 iterations, byte-granular rare path (one rank lookup
// per 8 cells). Halves hot-loop instructions and store-queue entries.
static constexpr int Bb      = 1024;
static constexpr int E       = 512;
static constexpr int Nn      = 256;
static constexpr int CELLS   = Nn * Nn;     // 65536 cells / batch
static constexpr int NWORDS  = CELLS / 32;  // 2048 bitmap words
static constexpr int TS      = 2048;        // hash slots (<=0.5 load)
static constexpr int THREADS = 512;
static constexpr int ITERS   = (CELLS / 8) / THREADS;   // 16 x 32B per thread
static constexpr int GROUP   = 4;                       // word prefetch depth

__device__ __forceinline__ uint32_t ht_hash(uint32_t key) {
    return (key * 2654435761u) >> (32 - 11);            // -> [0, 2048)
}

// Entry: key(16b hi) | prio(16b lo). key in [257,65535] so entry!=0 when valid.
// Returns the slot where `key` resides.
__device__ __forceinline__ uint32_t ht_insert(uint32_t* table, uint32_t key, uint32_t prio) {
    uint32_t entry = (key << 16) | prio;
    uint32_t h = ht_hash(key);
    #pragma unroll 1
    while (true) {
        uint32_t cur = table[h];
        if (cur == 0u) {
            uint32_t old = atomicCAS(&table[h], 0u, entry);
            if (old == 0u) return h;
            cur = old;
        }
        if ((cur >> 16) == key) {          // same cell: max prio wins (hi bits equal)
            atomicMax(&table[h], entry);
            return h;
        }
        h = (h + 1) & (TS - 1);
    }
}

__device__ __forceinline__ void stg256_cs(float* p, const float* v) {
    asm volatile("st.global.cs.v8.f32 [%0], {%1,%2,%3,%4,%5,%6,%7,%8};"
                 :: "l"(p), "f"(v[0]), "f"(v[1]), "f"(v[2]), "f"(v[3]),
                    "f"(v[4]), "f"(v[5]), "f"(v[6]), "f"(v[7])
                 : "memory");
}

__global__ __launch_bounds__(THREADS, 3)
void bond_weight_kernel(const float* __restrict__ weights,
                        const int*   __restrict__ bond_src,
                        const int*   __restrict__ bond_dst,
                        const int*   __restrict__ bond_type,
                        float*       __restrict__ out)
{
    __shared__ uint32_t table[TS];          // key|prio (8 KB)
    __shared__ uint32_t bitmap[NWORDS];     // occupied cells (8 KB)
    __shared__ uint16_t rankw[NWORDS];      // exclusive prefix popcount per word (4 KB)
    __shared__ float    cvals[2 * E];       // compact winner values, cell-id order (4 KB)
    __shared__ uint32_t warpsum[16];

    const int b = blockIdx.x;
    const int t = threadIdx.x;

    // ---- clear hash + bitmap ----
    #pragma unroll
    for (int i = 0; i < NWORDS / THREADS; i++) {
        table [t + i * THREADS] = 0u;
        bitmap[t + i * THREADS] = 0u;
    }

    // ---- this thread's edge ----
    const int   eidx = b * E + t;                  // 512 threads == 512 edges
    const int   s = bond_src[eidx] + 1;            // 1..255
    const int   d = bond_dst[eidx] + 1;
    const float w = weights[bond_type[eidx]];

    const uint32_t key1  = (uint32_t)(s * Nn + d); // pass 0: [src,dst]
    const uint32_t key2  = (uint32_t)(d * Nn + s); // pass 1: [dst,src]
    const uint32_t prio1 = (uint32_t)(t + 1);      // ref: pass0 e=0..E-1, then pass1;
    const uint32_t prio2 = (uint32_t)(E + t + 1);  // later application wins

    __syncthreads();   // clears visible

    const uint32_t slot1 = ht_insert(table, key1, prio1);
    const uint32_t slot2 = ht_insert(table, key2, prio2);
    atomicOr(&bitmap[key1 >> 5], 1u << (key1 & 31));
    atomicOr(&bitmap[key2 >> 5], 1u << (key2 & 31));

    __syncthreads();   // inserts + bitmap final

    // ---- block-wide exclusive prefix sum of per-word popcounts ----
    {
        const int base4 = t * 4;                   // 512 threads x 4 words = 2048
        const uint32_t c0 = __popc(bitmap[base4 + 0]);
        const uint32_t c1 = __popc(bitmap[base4 + 1]);
        const uint32_t c2 = __popc(bitmap[base4 + 2]);
        const uint32_t c3 = __popc(bitmap[base4 + 3]);
        const uint32_t ssum = c0 + c1 + c2 + c3;

        const uint32_t lane = t & 31, wrp = t >> 5;
        uint32_t x = ssum;
        #pragma unroll
        for (int off = 1; off < 32; off <<= 1) {
            uint32_t y = __shfl_up_sync(0xFFFFFFFFu, x, off);
            if (lane >= off) x += y;
        }
        if (lane == 31) warpsum[wrp] = x;          // warp totals (inclusive)
        __syncthreads();
        if (t == 0) {                              // serial scan of 16 warp totals
            uint32_t acc = 0;
            #pragma unroll
            for (int i = 0; i < 16; i++) { uint32_t v = warpsum[i]; warpsum[i] = acc; acc += v; }
        }
        __syncthreads();
        const uint32_t excl = warpsum[wrp] + (x - ssum);   // thread-exclusive prefix
        rankw[base4 + 0] = (uint16_t)(excl);
        rankw[base4 + 1] = (uint16_t)(excl + c0);
        rankw[base4 + 2] = (uint16_t)(excl + c0 + c1);
        rankw[base4 + 3] = (uint16_t)(excl + c0 + c1 + c2);
    }
    __syncthreads();   // rank ready

    // ---- winners deposit values at their compact (cell-id-ordered) position ----
    {
        if ((table[slot1] & 0xFFFFu) == prio1) {
            uint32_t wd = key1 >> 5, bt = key1 & 31;
            uint32_t pos = (uint32_t)rankw[wd] + __popc(bitmap[wd] & ((1u << bt) - 1u));
            cvals[pos] = w;
        }
        if ((table[slot2] & 0xFFFFu) == prio2) {
            uint32_t wd = key2 >> 5, bt = key2 & 31;
            uint32_t pos = (uint32_t)rankw[wd] + __popc(bitmap[wd] & ((1u << bt) - 1u));
            cvals[pos] = w;
        }
    }
    __syncthreads();   // cvals ready

    // ---- single streaming pass: 16 x 32B (STG.256) per thread ----
    // chunk c = i*512 + t covers floats [c*8, c*8+8); bitmap word = c>>2,
    // byte-in-word = (t & 3) (loop-invariant).
    float* obase = out + (size_t)b * CELLS + (size_t)t * 8u;
    const int      wsub  = t >> 2;                 // word column (128 words per row)
    const uint32_t sh    = (t & 3u) * 8u;          // byte shift (0/8/16/24)
    const uint32_t below = (1u << sh) - 1u;

    #pragma unroll
    for (int g = 0; g < ITERS / GROUP; g++) {
        uint32_t wbuf[GROUP];
        #pragma unroll
        for (int j = 0; j < GROUP; j++)            // batch the LDS loads
            wbuf[j] = bitmap[(g * GROUP + j) * 128 + wsub];
        #pragma unroll
        for (int j = 0; j < GROUP; j++) {
            const int i = g * GROUP + j;
            const uint32_t word = wbuf[j];
            const uint32_t byt  = (word >> sh) & 0xFFu;
            float v[8] = {0.f, 0.f, 0.f, 0.f, 0.f, 0.f, 0.f, 0.f};
            if (byt) {                             // one rank lookup per 8 cells
                uint32_t p = (uint32_t)rankw[i * 128 + wsub] + __popc(word & below);
                #pragma unroll
                for (int k = 0; k < 8; k++)
                    if (byt & (1u << k)) v[k] = cvals[p++];
            }
            stg256_cs(obase + (size_t)i * (THREADS * 8), v);
        }
    }
}

extern "C" void kernel_launch(void* const* d_in, const int* in_sizes, int n_in,
                              void* d_out, int out_size)
{
    const float* weights   = (const float*)d_in[0];
    const int*   bond_src  = (const int*)  d_in[1];
    const int*   bond_dst  = (const int*)  d_in[2];
    const int*   bond_type = (const int*)  d_in[3];
    float* out = (float*)d_out;

    bond_weight_kernel<<<Bb, THREADS>>>(weights, bond_src, bond_dst, bond_type, out);
}

// round 9
// speedup vs baseline: 1.0330x; 1.0330x over previous
#include <cuda_runtime.h>
#include <stdint.h>

// weights[T=8] f32; bond_src/dst/type [B=1024,E=512] i32 (+1 node offset);
// out [B,256,256] f32 (256 MiB).
// Fused single-pass (R4/R7 structure): per-batch smem hash dedup (reference
// last-write-wins order), bitmap + rank/popcount + compact values, then ONE
// pass writing every 128B line exactly once.
// R9 delta vs R7: PLAIN stores instead of __stcs. Under graph-replay steady
// state the output buffer is re-written every launch; default-policy stores
// let ~126MB of it stay dirty-resident in L2 and be overwritten in place,
// shifting the bottleneck from the DRAM write path to the LTS cap.
static constexpr int Bb      = 1024;
static constexpr int E       = 512;
static constexpr int Nn      = 256;
static constexpr int CELLS   = Nn * Nn;     // 65536 cells / batch
static constexpr int NWORDS  = CELLS / 32;  // 2048 bitmap words
static constexpr int TS      = 2048;        // hash slots (<=0.5 load)
static constexpr int THREADS = 512;
static constexpr int ITERS   = (CELLS / 4) / THREADS;   // 32 float4 per thread
static constexpr int GROUP   = 8;                       // prefetch depth

__device__ __forceinline__ uint32_t ht_hash(uint32_t key) {
    return (key * 2654435761u) >> (32 - 11);            // -> [0, 2048)
}

// Entry: key(16b hi) | prio(16b lo). key in [257,65535] so entry!=0 when valid.
// Returns the slot where `key` resides.
__device__ __forceinline__ uint32_t ht_insert(uint32_t* table, uint32_t key, uint32_t prio) {
    uint32_t entry = (key << 16) | prio;
    uint32_t h = ht_hash(key);
    #pragma unroll 1
    while (true) {
        uint32_t cur = table[h];
        if (cur == 0u) {
            uint32_t old = atomicCAS(&table[h], 0u, entry);
            if (old == 0u) return h;
            cur = old;
        }
        if ((cur >> 16) == key) {          // same cell: max prio wins (hi bits equal)
            atomicMax(&table[h], entry);
            return h;
        }
        h = (h + 1) & (TS - 1);
    }
}

__global__ __launch_bounds__(THREADS, 3)
void bond_weight_kernel(const float* __restrict__ weights,
                        const int*   __restrict__ bond_src,
                        const int*   __restrict__ bond_dst,
                        const int*   __restrict__ bond_type,
                        float*       __restrict__ out)
{
    __shared__ uint32_t table[TS];          // key|prio (8 KB)
    __shared__ uint32_t bitmap[NWORDS];     // occupied cells (8 KB)
    __shared__ uint16_t rankw[NWORDS];      // exclusive prefix popcount per word (4 KB)
    __shared__ float    cvals[2 * E];       // compact winner values, cell-id order (4 KB)
    __shared__ uint32_t warpsum[16];

    const int b = blockIdx.x;
    const int t = threadIdx.x;

    // ---- clear hash + bitmap ----
    #pragma unroll
    for (int i = 0; i < NWORDS / THREADS; i++) {
        table [t + i * THREADS] = 0u;
        bitmap[t + i * THREADS] = 0u;
    }

    // ---- this thread's edge ----
    const int   eidx = b * E + t;                  // 512 threads == 512 edges
    const int   s = bond_src[eidx] + 1;            // 1..255
    const int   d = bond_dst[eidx] + 1;
    const float w = weights[bond_type[eidx]];

    const uint32_t key1  = (uint32_t)(s * Nn + d); // pass 0: [src,dst]
    const uint32_t key2  = (uint32_t)(d * Nn + s); // pass 1: [dst,src]
    const uint32_t prio1 = (uint32_t)(t + 1);      // ref: pass0 e=0..E-1, then pass1;
    const uint32_t prio2 = (uint32_t)(E + t + 1);  // later application wins

    __syncthreads();   // clears visible

    const uint32_t slot1 = ht_insert(table, key1, prio1);
    const uint32_t slot2 = ht_insert(table, key2, prio2);
    atomicOr(&bitmap[key1 >> 5], 1u << (key1 & 31));
    atomicOr(&bitmap[key2 >> 5], 1u << (key2 & 31));

    __syncthreads();   // inserts + bitmap final

    // ---- block-wide exclusive prefix sum of per-word popcounts ----
    {
        const int base4 = t * 4;                   // 512 threads x 4 words = 2048
        const uint32_t c0 = __popc(bitmap[base4 + 0]);
        const uint32_t c1 = __popc(bitmap[base4 + 1]);
        const uint32_t c2 = __popc(bitmap[base4 + 2]);
        const uint32_t c3 = __popc(bitmap[base4 + 3]);
        const uint32_t ssum = c0 + c1 + c2 + c3;

        const uint32_t lane = t & 31, wrp = t >> 5;
        uint32_t x = ssum;
        #pragma unroll
        for (int off = 1; off < 32; off <<= 1) {
            uint32_t y = __shfl_up_sync(0xFFFFFFFFu, x, off);
            if (lane >= off) x += y;
        }
        if (lane == 31) warpsum[wrp] = x;          // warp totals (inclusive)
        __syncthreads();
        if (t == 0) {                              // serial scan of 16 warp totals
            uint32_t acc = 0;
            #pragma unroll
            for (int i = 0; i < 16; i++) { uint32_t v = warpsum[i]; warpsum[i] = acc; acc += v; }
        }
        __syncthreads();
        const uint32_t excl = warpsum[wrp] + (x - ssum);   // thread-exclusive prefix
        rankw[base4 + 0] = (uint16_t)(excl);
        rankw[base4 + 1] = (uint16_t)(excl + c0);
        rankw[base4 + 2] = (uint16_t)(excl + c0 + c1);
        rankw[base4 + 3] = (uint16_t)(excl + c0 + c1 + c2);
    }
    __syncthreads();   // rank ready

    // ---- winners deposit values at their compact (cell-id-ordered) position ----
    {
        if ((table[slot1] & 0xFFFFu) == prio1) {
            uint32_t wd = key1 >> 5, bt = key1 & 31;
            uint32_t pos = (uint32_t)rankw[wd] + __popc(bitmap[wd] & ((1u << bt) - 1u));
            cvals[pos] = w;
        }
        if ((table[slot2] & 0xFFFFu) == prio2) {
            uint32_t wd = key2 >> 5, bt = key2 & 31;
            uint32_t pos = (uint32_t)rankw[wd] + __popc(bitmap[wd] & ((1u << bt) - 1u));
            cvals[pos] = w;
        }
    }
    __syncthreads();   // cvals ready

    // ---- single pass; 8-deep bitmap-word prefetch; PLAIN 128-bit stores ----
    float4* o4 = reinterpret_cast<float4*>(out + (size_t)b * CELLS);
    const float4 z = make_float4(0.f, 0.f, 0.f, 0.f);
    const int      wsub = t >> 3;            // word sub-index (8 float4 per word)
    const uint32_t sh   = (t & 7u) * 4u;     // loop-invariant nibble shift
    const uint32_t below = (1u << sh) - 1u;

    #pragma unroll
    for (int g = 0; g < ITERS / GROUP; g++) {
        uint32_t wbuf[GROUP];
        #pragma unroll
        for (int j = 0; j < GROUP; j++)                      // 8 LDS in flight
            wbuf[j] = bitmap[(g * GROUP + j) * 64 + wsub];
        #pragma unroll
        for (int j = 0; j < GROUP; j++) {
            const int i   = g * GROUP + j;
            const int idx = i * THREADS + t;                 // coalesced float4 index
            const uint32_t word = wbuf[j];
            const uint32_t nib  = (word >> sh) & 0xFu;
            float4 v = z;
            if (nib) {                                       // O(1) rare-path
                uint32_t p = (uint32_t)rankw[i * 64 + wsub] + __popc(word & below);
                if (nib & 1u) v.x = cvals[p++];
                if (nib & 2u) v.y = cvals[p++];
                if (nib & 4u) v.z = cvals[p++];
                if (nib & 8u) v.w = cvals[p];
            }
            o4[idx] = v;     // PLAIN store: let the line stay dirty in L2 and be
        }                    // overwritten in place by the next replay
    }
}

extern "C" void kernel_launch(void* const* d_in, const int* in_sizes, int n_in,
                              void* d_out, int out_size)
{
    const float* weights   = (const float*)d_in[0];
    const int*   bond_src  = (const int*)  d_in[1];
    const int*   bond_dst  = (const int*)  d_in[2];
    const int*   bond_type = (const int*)  d_in[3];
    float* out = (float*)d_out;

    bond_weight_kernel<<<Bb, THREADS>>>(weights, bond_src, bond_dst, bond_type, out);
}